// round 15
// baseline (speedup 1.0000x reference)
#include <cuda_runtime.h>
#include <cuda_bf16.h>
#include <cuda_fp16.h>
#include <cstdint>

#define KTOT (768*768)   // 589824
#define LDK1 208         // X/Y padded K (196 -> 208)

// fp16 input planes
static __device__ __align__(16) __half g_Xh[(size_t)64*768*LDK1];  // 20.4 MB
static __device__ __align__(16) __half g_Yh[(size_t)64*768*LDK1];
static __device__ __align__(16) __half g_w0h[(size_t)64*768*32];   // 3.1 MB, unpadded
static __device__ __align__(16) __half g_w1h[(size_t)64*768*32];
// fp16 planes of G[b,c,c'] and W[n,c,c']  (75.5 MB each)
static __device__ __align__(16) __half g_Gh[(size_t)64*KTOT];
static __device__ __align__(16) __half g_Wh[(size_t)64*KTOT];
static __device__ float g_Zp[576*64*64];   // split-K partials (deterministic)

// ---------------------------------------------------------------------------
// helpers
// ---------------------------------------------------------------------------
__device__ __forceinline__ uint32_t smem_u32(const void* p) {
    uint32_t a;
    asm("{ .reg .u64 t; cvta.to.shared.u64 t, %1; cvt.u32.u64 %0, t; }" : "=r"(a) : "l"(p));
    return a;
}
#define SW128(o) ((o) ^ (((o) >> 3) & 0x70))

__device__ __forceinline__ void cpasync16(uint32_t dst, const void* src) {
    asm volatile("cp.async.cg.shared.global [%0], [%1], 16;" :: "r"(dst), "l"(src));
}
#define CP_COMMIT() asm volatile("cp.async.commit_group;" ::: "memory")
#define CP_WAIT(n)  asm volatile("cp.async.wait_group %0;" :: "n"(n) : "memory")

__device__ __forceinline__ void ldsm4(uint32_t* r, uint32_t addr) {
    asm volatile("ldmatrix.sync.aligned.m8n8.x4.shared.b16 {%0,%1,%2,%3}, [%4];"
                 : "=r"(r[0]), "=r"(r[1]), "=r"(r[2]), "=r"(r[3]) : "r"(addr));
}
__device__ __forceinline__ void mma_fp16(float* c, const uint32_t* a, uint32_t b0, uint32_t b1) {
    asm volatile("mma.sync.aligned.m16n8k16.row.col.f32.f16.f16.f32 "
                 "{%0,%1,%2,%3}, {%4,%5,%6,%7}, {%8,%9}, {%0,%1,%2,%3};"
                 : "+f"(c[0]), "+f"(c[1]), "+f"(c[2]), "+f"(c[3])
                 : "r"(a[0]), "r"(a[1]), "r"(a[2]), "r"(a[3]), "r"(b0), "r"(b1));
}

// 128x128 warp-MMA over [128 rows][64 halves] SW128 tiles; nks k-steps of 16.
__device__ __forceinline__ void compute_chunk(
    float acc[2][8][4], uint32_t aBase, uint32_t bBase, int wm, int wn, int lane, int nks)
{
    const int lrow = lane & 15, lseg = lane >> 4;
#pragma unroll
    for (int ks = 0; ks < 4; ks++) {
        if (ks >= nks) break;
        uint32_t afr[2][4];
#pragma unroll
        for (int mi = 0; mi < 2; mi++) {
            int row = wm * 32 + mi * 16 + lrow;
            ldsm4(afr[mi], aBase + SW128((uint32_t)(row * 128 + ks * 32 + lseg * 16)));
        }
#pragma unroll
        for (int nj = 0; nj < 4; nj++) {
            uint32_t bfr[4];
            int row = wn * 64 + nj * 16 + lrow;
            ldsm4(bfr, bBase + SW128((uint32_t)(row * 128 + ks * 32 + lseg * 16)));
#pragma unroll
            for (int mi = 0; mi < 2; mi++) {
                mma_fp16(acc[mi][nj * 2],     afr[mi], bfr[0], bfr[2]);
                mma_fp16(acc[mi][nj * 2 + 1], afr[mi], bfr[1], bfr[3]);
            }
        }
    }
}

// ---------------------------------------------------------------------------
// Prep: fp32 -> fp16 planes. X/Y: 196 -> 208 cols; w: 32 cols unpadded.
// grid 11520 x 256 (exact).
// ---------------------------------------------------------------------------
__global__ void prep_kernel(const float* __restrict__ X, const float* __restrict__ Y,
                            const float* __restrict__ w)
{
    const long n1 = (long)64 * 768 * 26;   // uint4 slots per X/Y plane
    const long n3 = (long)64 * 768 * 4;    // uint4 slots per w plane (32 cols)
    long s = (long)blockIdx.x * 256 + threadIdx.x;
    union { __half h[8]; uint4 u; } o;
    if (s < 2 * n1) {
        const float* src = (s < n1) ? X : Y;
        __half* dst = (s < n1) ? g_Xh : g_Yh;
        long t = (s < n1) ? s : s - n1;
        long row = t / 26;
        int slot = (int)(t % 26);
        int k0 = slot * 8;
        if (slot < 23) {
            float4 p0 = *(const float4*)&src[row * 196 + k0];
            float4 p1 = *(const float4*)&src[row * 196 + k0 + 4];
            o.h[0] = __float2half(p0.x); o.h[1] = __float2half(p0.y);
            o.h[2] = __float2half(p0.z); o.h[3] = __float2half(p0.w);
            o.h[4] = __float2half(p1.x); o.h[5] = __float2half(p1.y);
            o.h[6] = __float2half(p1.z); o.h[7] = __float2half(p1.w);
        } else {
#pragma unroll
            for (int j = 0; j < 8; j++) {
                int k = k0 + j;
                o.h[j] = (k < 196) ? __float2half(src[row * 196 + k]) : __half(0.0f);
            }
        }
        *(uint4*)&dst[row * LDK1 + k0] = o.u;
    } else {
        long t = s - 2 * n1;
        const float* src = (t < n3) ? w : (w + (long)64 * 768 * 32);
        __half* dst = (t < n3) ? g_w0h : g_w1h;
        long u2 = (t < n3) ? t : t - n3;
        long row = u2 >> 2;
        int k0 = (int)(u2 & 3) << 3;
        float4 p0 = *(const float4*)&src[row * 32 + k0];
        float4 p1 = *(const float4*)&src[row * 32 + k0 + 4];
        o.h[0] = __float2half(p0.x); o.h[1] = __float2half(p0.y);
        o.h[2] = __float2half(p0.z); o.h[3] = __float2half(p0.w);
        o.h[4] = __float2half(p1.x); o.h[5] = __float2half(p1.y);
        o.h[6] = __float2half(p1.z); o.h[7] = __float2half(p1.w);
        *(uint4*)&dst[row * 32 + k0] = o.u;
    }
}

// ---------------------------------------------------------------------------
// Unified Gram GEMM (round-13 form): grid (6,6,128), 2 CTAs/SM, interleaved:
//   bz even: G[bz/2] = Xh @ Yh^T (ldk=208; 4 chunks, ksteps {4,4,4,1})
//   bz odd : W[bz/2] = w0h @ w1h^T (ldk=32; 1 chunk, 2 ksteps)
// 3-stage cp.async, distance-2 prefetch, issue-before-wait. dyn smem 98304.
// ---------------------------------------------------------------------------
__global__ void __launch_bounds__(256, 2) gemm_unified()
{
    extern __shared__ char dsm[];
    const int tid = threadIdx.x, lane = tid & 31, wid = tid >> 5;
    const int wm = wid & 3, wn = wid >> 2;
    const int bx = blockIdx.x, by = blockIdx.y, bzr = blockIdx.z;
    const bool isW = (bzr & 1);
    const int  idx = bzr >> 1;        // batch b (G) or output n (W)

    const __half* Ap;
    const __half* Bp;
    int ldk, nCh;
    if (isW) {
        Ap = g_w0h + (size_t)idx * 768 * 32;
        Bp = g_w1h + (size_t)idx * 768 * 32;
        ldk = 32; nCh = 1;
    } else {
        Ap = g_Xh + (size_t)idx * 768 * LDK1;
        Bp = g_Yh + (size_t)idx * 768 * LDK1;
        ldk = LDK1; nCh = 4;
    }
    const __half* Ab = Ap + (size_t)(by * 128) * ldk;
    const __half* Bb = Bp + (size_t)(bx * 128) * ldk;

    uint32_t tBase[3][2];   // [buf][A/B]
#pragma unroll
    for (int q = 0; q < 3; q++) {
        tBase[q][0] = smem_u32(dsm) + q * 32768;
        tBase[q][1] = tBase[q][0] + 16384;
    }

    auto issue = [&](int ch, int q, int kgmax) {
#pragma unroll
        for (int it = 0; it < 8; it++) {
            int t   = tid + it * 256;     // 0..2047
            int m   = t >> 10;            // 0=A, 1=B
            int rem = t & 1023;
            int row = rem >> 3;
            int kg  = rem & 7;
            if (kg < kgmax) {
                const __half* src = (m ? Bb : Ab) + (size_t)row * ldk + ch * 64 + kg * 8;
                cpasync16(tBase[q][m] + SW128((uint32_t)(row * 128 + kg * 16)), src);
            }
        }
    };

    float acc[2][8][4];
#pragma unroll
    for (int i = 0; i < 2; i++)
#pragma unroll
        for (int j = 0; j < 8; j++)
#pragma unroll
            for (int q = 0; q < 4; q++) acc[i][j][q] = 0.0f;

    // pipeline prologue: prefetch up to 2 chunks
    issue(0, 0, isW ? 4 : 8);
    CP_COMMIT();
    if (nCh > 1) { issue(1, 1, 8); CP_COMMIT(); }

    for (int ch = 0; ch < nCh; ch++) {
        if (ch + 2 < nCh) {
            issue(ch + 2, (ch + 2) % 3, (ch + 2 < 3) ? 8 : 2);
            CP_COMMIT();
            CP_WAIT(2);
        } else if (ch + 1 < nCh) {
            CP_WAIT(1);
        } else {
            CP_WAIT(0);
        }
        __syncthreads();
        int nks = isW ? 2 : (ch < 3 ? 4 : 1);
        compute_chunk(acc, tBase[ch % 3][0], tBase[ch % 3][1], wm, wn, lane, nks);
        __syncthreads();
    }

    // epilogue: fragments -> half2 -> smem fp16 [128][68 u32 pitch] -> global
    uint32_t* Sh = (uint32_t*)dsm;
#pragma unroll
    for (int mi = 0; mi < 2; mi++)
#pragma unroll
        for (int ni = 0; ni < 8; ni++) {
            int r  = wm * 32 + mi * 16 + (lane >> 2);
            int c2 = wn * 32 + ni * 4 + (lane & 3);
            __half2 h0 = __floats2half2_rn(acc[mi][ni][0], acc[mi][ni][1]);
            __half2 h1 = __floats2half2_rn(acc[mi][ni][2], acc[mi][ni][3]);
            Sh[r * 68 + c2]       = *(uint32_t*)&h0;
            Sh[(r + 8) * 68 + c2] = *(uint32_t*)&h1;
        }
    __syncthreads();

    __half* Oh = (isW ? g_Wh : g_Gh) + (size_t)idx * KTOT;
#pragma unroll
    for (int it = 0; it < 8; it++) {
        int i2  = tid + it * 256;      // 2048 uint4 = 128 rows x 16
        int row = i2 >> 4;
        int c4  = (i2 & 15) * 4;
        uint4 v = *(const uint4*)&Sh[row * 68 + c4];
        *(uint4*)&Oh[(size_t)(by * 128 + row) * 768 + bx * 128 + c4 * 2] = v;
    }
}

// ---------------------------------------------------------------------------
// Stage 3: split-K contraction, 64x64 output per CTA.
// 576 CTAs x 1024-k slices, 16 chunks of 64.
// 4 buffers (64KB static) -> distance-3 prefetch with ONE barrier per chunk:
//   wait -> sync -> issue(ch+3) into (ch+3)%4 (= (ch-1)%4, freed by
//   compute(ch-1), ordered by this sync) -> compute(ch).
// ---------------------------------------------------------------------------
__global__ void __launch_bounds__(256) contract_kernel()
{
    __shared__ __align__(128) char sm[65536];   // 4 bufs x (A 8KB + B 8KB)
    const int tid = threadIdx.x, lane = tid & 31, wid = tid >> 5;
    const int wm = wid & 3, wn = wid >> 2;
    const int lrow = lane & 15, lseg = lane >> 4;

    uint32_t tBase[4][2];
#pragma unroll
    for (int q = 0; q < 4; q++) {
        tBase[q][0] = smem_u32(sm) + q * 16384;
        tBase[q][1] = tBase[q][0] + 8192;
    }

    auto issue = [&](int ch, int q) {
        const long k0 = (long)blockIdx.x * 1024 + ch * 64;
#pragma unroll
        for (int it = 0; it < 4; it++) {
            int t   = tid + it * 256;   // 0..1023
            int m   = t >> 9;           // 0 = G(A), 1 = W(B)
            int rem = t & 511;
            int row = rem >> 3;         // 0..63
            int kg  = rem & 7;
            const __half* src = (m ? g_Wh : g_Gh) + (size_t)row * KTOT + k0 + kg * 8;
            cpasync16(tBase[q][m] + SW128((uint32_t)(row * 128 + kg * 16)), src);
        }
    };

    float acc[4][4];
#pragma unroll
    for (int j = 0; j < 4; j++)
#pragma unroll
        for (int q = 0; q < 4; q++) acc[j][q] = 0.0f;

    // prologue: 3 chunks in flight
    issue(0, 0); CP_COMMIT();
    issue(1, 1); CP_COMMIT();
    issue(2, 2); CP_COMMIT();

    for (int ch = 0; ch < 16; ch++) {
        // groups pending after this wait: chunks ch+1..min(15,ch+2)
        if (ch <= 13)      CP_WAIT(2);
        else if (ch == 14) CP_WAIT(1);
        else               CP_WAIT(0);
        __syncthreads();
        if (ch + 3 < 16) {
            issue(ch + 3, (ch + 3) & 3);
            CP_COMMIT();
        }
        uint32_t aBase = tBase[ch & 3][0], bBase = tBase[ch & 3][1];
#pragma unroll
        for (int ks = 0; ks < 4; ks++) {
            uint32_t afr[4];
            int arow = wm * 16 + lrow;
            ldsm4(afr, aBase + SW128((uint32_t)(arow * 128 + ks * 32 + lseg * 16)));
#pragma unroll
            for (int nj = 0; nj < 2; nj++) {
                uint32_t bfr[4];
                int brow = wn * 32 + nj * 16 + lrow;
                ldsm4(bfr, bBase + SW128((uint32_t)(brow * 128 + ks * 32 + lseg * 16)));
                mma_fp16(acc[nj * 2],     afr, bfr[0], bfr[2]);
                mma_fp16(acc[nj * 2 + 1], afr, bfr[1], bfr[3]);
            }
        }
    }

    float* outp = g_Zp + (size_t)blockIdx.x * 4096;
#pragma unroll
    for (int nj = 0; nj < 4; nj++) {
        int r = wm * 16 + (lane >> 2);
        int c = wn * 32 + nj * 8 + (lane & 3) * 2;
        *(float2*)&outp[r * 64 + c]       = make_float2(acc[nj][0], acc[nj][1]);
        *(float2*)&outp[(r + 8) * 64 + c] = make_float2(acc[nj][2], acc[nj][3]);
    }
}

// ---------------------------------------------------------------------------
// Fused reduce (576 partials, 16-way split) + softmax. 64 CTAs x 1024 thr.
// ---------------------------------------------------------------------------
__global__ void __launch_bounds__(1024) reduce_softmax_kernel(
    const float* __restrict__ bias, float* __restrict__ out)
{
    const int b = blockIdx.x;
    const int g = threadIdx.x >> 6, n = threadIdx.x & 63;   // 16 groups x 64 n
    __shared__ float sd[16][64];
    __shared__ float red[64];

    float s = 0.0f;
#pragma unroll
    for (int u = 0; u < 36; u++)
        s += g_Zp[(size_t)(g + u * 16) * 4096 + b * 64 + n];
    sd[g][n] = s;
    __syncthreads();

    for (int off = 8; off > 0; off >>= 1) {
        if (g < off) sd[g][n] += sd[g + off][n];
        __syncthreads();
    }

    float z = 0.0f;
    if (g == 0) {
        z = sd[0][n] * (1.0f / 196.0f) + bias[n];
        red[n] = z;
    }
    __syncthreads();
    for (int off = 32; off > 0; off >>= 1) {
        if (g == 0 && n < off) red[n] = fmaxf(red[n], red[n + off]);
        __syncthreads();
    }
    float m = red[0];
    __syncthreads();
    float e = 0.0f;
    if (g == 0) { e = expf(z - m); red[n] = e; }
    __syncthreads();
    for (int off = 32; off > 0; off >>= 1) {
        if (g == 0 && n < off) red[n] += red[n + off];
        __syncthreads();
    }
    if (g == 0) out[b * 64 + n] = e / red[0];
}

// ---------------------------------------------------------------------------
// Launch
// ---------------------------------------------------------------------------
extern "C" void kernel_launch(void* const* d_in, const int* in_sizes, int n_in,
                              void* d_out, int out_size) {
    const float* X    = (const float*)d_in[0];  // [64, 768, 14, 14]
    const float* Y    = (const float*)d_in[1];  // [64, 768, 14, 14]
    const float* w    = (const float*)d_in[2];  // [2, 64, 768, 32]
    const float* bias = (const float*)d_in[3];  // [64]
    float* out = (float*)d_out;                 // [64, 64]

    // Idempotent, not a stream op — safe under graph capture.
    cudaFuncSetAttribute(gemm_unified, cudaFuncAttributeMaxDynamicSharedMemorySize, 98304);

    // Stage 0: fp32 -> fp16 planes
    prep_kernel<<<11520, 256>>>(X, Y, w);

    // Stages 1+2 fused + wave-interleaved: Gram of (X,Y) and of (w0,w1)
    {
        dim3 grid(6, 6, 128);
        gemm_unified<<<grid, 256, 98304>>>();
    }

    // Stage 3: split-K contraction (4-buffer, single barrier, distance-3)
    contract_kernel<<<576, 256>>>();

    // Stage 3b+4: fused deterministic reduce + softmax
    reduce_softmax_kernel<<<64, 1024>>>(bias, out);
}

// round 16
// speedup vs baseline: 1.0326x; 1.0326x over previous
#include <cuda_runtime.h>
#include <cuda_bf16.h>
#include <cuda_fp16.h>
#include <cstdint>

#define KTOT (768*768)   // 589824
#define LDK1 208         // X/Y padded K (196 -> 208)

// fp16 input planes
static __device__ __align__(16) __half g_Xh[(size_t)64*768*LDK1];  // 20.4 MB
static __device__ __align__(16) __half g_Yh[(size_t)64*768*LDK1];
static __device__ __align__(16) __half g_w0h[(size_t)64*768*32];   // 3.1 MB, unpadded
static __device__ __align__(16) __half g_w1h[(size_t)64*768*32];
// fp16 planes of G[b,c,c'] and W[n,c,c']  (75.5 MB each)
static __device__ __align__(16) __half g_Gh[(size_t)64*KTOT];
static __device__ __align__(16) __half g_Wh[(size_t)64*KTOT];
static __device__ float g_Zp[576*64*64];   // split-K partials (deterministic)

// ---------------------------------------------------------------------------
// helpers
// ---------------------------------------------------------------------------
__device__ __forceinline__ uint32_t smem_u32(const void* p) {
    uint32_t a;
    asm("{ .reg .u64 t; cvta.to.shared.u64 t, %1; cvt.u32.u64 %0, t; }" : "=r"(a) : "l"(p));
    return a;
}
#define SW128(o) ((o) ^ (((o) >> 3) & 0x70))

__device__ __forceinline__ void cpasync16(uint32_t dst, const void* src) {
    asm volatile("cp.async.cg.shared.global [%0], [%1], 16;" :: "r"(dst), "l"(src));
}
#define CP_COMMIT() asm volatile("cp.async.commit_group;" ::: "memory")
#define CP_WAIT(n)  asm volatile("cp.async.wait_group %0;" :: "n"(n) : "memory")

__device__ __forceinline__ void ldsm4(uint32_t* r, uint32_t addr) {
    asm volatile("ldmatrix.sync.aligned.m8n8.x4.shared.b16 {%0,%1,%2,%3}, [%4];"
                 : "=r"(r[0]), "=r"(r[1]), "=r"(r[2]), "=r"(r[3]) : "r"(addr));
}
__device__ __forceinline__ void mma_fp16(float* c, const uint32_t* a, uint32_t b0, uint32_t b1) {
    asm volatile("mma.sync.aligned.m16n8k16.row.col.f32.f16.f16.f32 "
                 "{%0,%1,%2,%3}, {%4,%5,%6,%7}, {%8,%9}, {%0,%1,%2,%3};"
                 : "+f"(c[0]), "+f"(c[1]), "+f"(c[2]), "+f"(c[3])
                 : "r"(a[0]), "r"(a[1]), "r"(a[2]), "r"(a[3]), "r"(b0), "r"(b1));
}

// 128x128 warp-MMA over [128 rows][64 halves] SW128 tiles; nks k-steps of 16.
__device__ __forceinline__ void compute_chunk(
    float acc[2][8][4], uint32_t aBase, uint32_t bBase, int wm, int wn, int lane, int nks)
{
    const int lrow = lane & 15, lseg = lane >> 4;
#pragma unroll
    for (int ks = 0; ks < 4; ks++) {
        if (ks >= nks) break;
        uint32_t afr[2][4];
#pragma unroll
        for (int mi = 0; mi < 2; mi++) {
            int row = wm * 32 + mi * 16 + lrow;
            ldsm4(afr[mi], aBase + SW128((uint32_t)(row * 128 + ks * 32 + lseg * 16)));
        }
#pragma unroll
        for (int nj = 0; nj < 4; nj++) {
            uint32_t bfr[4];
            int row = wn * 64 + nj * 16 + lrow;
            ldsm4(bfr, bBase + SW128((uint32_t)(row * 128 + ks * 32 + lseg * 16)));
#pragma unroll
            for (int mi = 0; mi < 2; mi++) {
                mma_fp16(acc[mi][nj * 2],     afr[mi], bfr[0], bfr[2]);
                mma_fp16(acc[mi][nj * 2 + 1], afr[mi], bfr[1], bfr[3]);
            }
        }
    }
}

// ---------------------------------------------------------------------------
// Prep: fp32 -> fp16 planes. X/Y: 196 -> 208 cols; w: 32 cols unpadded.
// grid 11520 x 256 (exact).
// ---------------------------------------------------------------------------
__global__ void prep_kernel(const float* __restrict__ X, const float* __restrict__ Y,
                            const float* __restrict__ w)
{
    const long n1 = (long)64 * 768 * 26;   // uint4 slots per X/Y plane
    const long n3 = (long)64 * 768 * 4;    // uint4 slots per w plane (32 cols)
    long s = (long)blockIdx.x * 256 + threadIdx.x;
    union { __half h[8]; uint4 u; } o;
    if (s < 2 * n1) {
        const float* src = (s < n1) ? X : Y;
        __half* dst = (s < n1) ? g_Xh : g_Yh;
        long t = (s < n1) ? s : s - n1;
        long row = t / 26;
        int slot = (int)(t % 26);
        int k0 = slot * 8;
        if (slot < 23) {
            float4 p0 = *(const float4*)&src[row * 196 + k0];
            float4 p1 = *(const float4*)&src[row * 196 + k0 + 4];
            o.h[0] = __float2half(p0.x); o.h[1] = __float2half(p0.y);
            o.h[2] = __float2half(p0.z); o.h[3] = __float2half(p0.w);
            o.h[4] = __float2half(p1.x); o.h[5] = __float2half(p1.y);
            o.h[6] = __float2half(p1.z); o.h[7] = __float2half(p1.w);
        } else {
#pragma unroll
            for (int j = 0; j < 8; j++) {
                int k = k0 + j;
                o.h[j] = (k < 196) ? __float2half(src[row * 196 + k]) : __half(0.0f);
            }
        }
        *(uint4*)&dst[row * LDK1 + k0] = o.u;
    } else {
        long t = s - 2 * n1;
        const float* src = (t < n3) ? w : (w + (long)64 * 768 * 32);
        __half* dst = (t < n3) ? g_w0h : g_w1h;
        long u2 = (t < n3) ? t : t - n3;
        long row = u2 >> 2;
        int k0 = (int)(u2 & 3) << 3;
        float4 p0 = *(const float4*)&src[row * 32 + k0];
        float4 p1 = *(const float4*)&src[row * 32 + k0 + 4];
        o.h[0] = __float2half(p0.x); o.h[1] = __float2half(p0.y);
        o.h[2] = __float2half(p0.z); o.h[3] = __float2half(p0.w);
        o.h[4] = __float2half(p1.x); o.h[5] = __float2half(p1.y);
        o.h[6] = __float2half(p1.z); o.h[7] = __float2half(p1.w);
        *(uint4*)&dst[row * 32 + k0] = o.u;
    }
}

// ---------------------------------------------------------------------------
// Unified Gram GEMM (round-13 form): grid (6,6,128), 2 CTAs/SM, interleaved:
//   bz even: G[bz/2] = Xh @ Yh^T (ldk=208; 4 chunks, ksteps {4,4,4,1})
//   bz odd : W[bz/2] = w0h @ w1h^T (ldk=32; 1 chunk, 2 ksteps)
// 3-stage cp.async, distance-2 prefetch, issue-before-wait. dyn smem 98304.
// ---------------------------------------------------------------------------
__global__ void __launch_bounds__(256, 2) gemm_unified()
{
    extern __shared__ char dsm[];
    const int tid = threadIdx.x, lane = tid & 31, wid = tid >> 5;
    const int wm = wid & 3, wn = wid >> 2;
    const int bx = blockIdx.x, by = blockIdx.y, bzr = blockIdx.z;
    const bool isW = (bzr & 1);
    const int  idx = bzr >> 1;        // batch b (G) or output n (W)

    const __half* Ap;
    const __half* Bp;
    int ldk, nCh;
    if (isW) {
        Ap = g_w0h + (size_t)idx * 768 * 32;
        Bp = g_w1h + (size_t)idx * 768 * 32;
        ldk = 32; nCh = 1;
    } else {
        Ap = g_Xh + (size_t)idx * 768 * LDK1;
        Bp = g_Yh + (size_t)idx * 768 * LDK1;
        ldk = LDK1; nCh = 4;
    }
    const __half* Ab = Ap + (size_t)(by * 128) * ldk;
    const __half* Bb = Bp + (size_t)(bx * 128) * ldk;

    uint32_t tBase[3][2];   // [buf][A/B]
#pragma unroll
    for (int q = 0; q < 3; q++) {
        tBase[q][0] = smem_u32(dsm) + q * 32768;
        tBase[q][1] = tBase[q][0] + 16384;
    }

    auto issue = [&](int ch, int q, int kgmax) {
#pragma unroll
        for (int it = 0; it < 8; it++) {
            int t   = tid + it * 256;     // 0..2047
            int m   = t >> 10;            // 0=A, 1=B
            int rem = t & 1023;
            int row = rem >> 3;
            int kg  = rem & 7;
            if (kg < kgmax) {
                const __half* src = (m ? Bb : Ab) + (size_t)row * ldk + ch * 64 + kg * 8;
                cpasync16(tBase[q][m] + SW128((uint32_t)(row * 128 + kg * 16)), src);
            }
        }
    };

    float acc[2][8][4];
#pragma unroll
    for (int i = 0; i < 2; i++)
#pragma unroll
        for (int j = 0; j < 8; j++)
#pragma unroll
            for (int q = 0; q < 4; q++) acc[i][j][q] = 0.0f;

    // pipeline prologue: prefetch up to 2 chunks
    issue(0, 0, isW ? 4 : 8);
    CP_COMMIT();
    if (nCh > 1) { issue(1, 1, 8); CP_COMMIT(); }

    for (int ch = 0; ch < nCh; ch++) {
        if (ch + 2 < nCh) {
            issue(ch + 2, (ch + 2) % 3, (ch + 2 < 3) ? 8 : 2);
            CP_COMMIT();
            CP_WAIT(2);
        } else if (ch + 1 < nCh) {
            CP_WAIT(1);
        } else {
            CP_WAIT(0);
        }
        __syncthreads();
        int nks = isW ? 2 : (ch < 3 ? 4 : 1);
        compute_chunk(acc, tBase[ch % 3][0], tBase[ch % 3][1], wm, wn, lane, nks);
        __syncthreads();
    }

    // epilogue: fragments -> half2 -> smem fp16 [128][68 u32 pitch] -> global
    uint32_t* Sh = (uint32_t*)dsm;
#pragma unroll
    for (int mi = 0; mi < 2; mi++)
#pragma unroll
        for (int ni = 0; ni < 8; ni++) {
            int r  = wm * 32 + mi * 16 + (lane >> 2);
            int c2 = wn * 32 + ni * 4 + (lane & 3);
            __half2 h0 = __floats2half2_rn(acc[mi][ni][0], acc[mi][ni][1]);
            __half2 h1 = __floats2half2_rn(acc[mi][ni][2], acc[mi][ni][3]);
            Sh[r * 68 + c2]       = *(uint32_t*)&h0;
            Sh[(r + 8) * 68 + c2] = *(uint32_t*)&h1;
        }
    __syncthreads();

    __half* Oh = (isW ? g_Wh : g_Gh) + (size_t)idx * KTOT;
#pragma unroll
    for (int it = 0; it < 8; it++) {
        int i2  = tid + it * 256;      // 2048 uint4 = 128 rows x 16
        int row = i2 >> 4;
        int c4  = (i2 & 15) * 4;
        uint4 v = *(const uint4*)&Sh[row * 68 + c4];
        *(uint4*)&Oh[(size_t)(by * 128 + row) * 768 + bx * 128 + c4 * 2] = v;
    }
}

// ---------------------------------------------------------------------------
// Stage 3 (round-13 form): split-K contraction, 64x64 output per CTA.
// 576 CTAs x 1024-k slices, 16 chunks of 64, 3-stage cp.async (49KB -> 4 CTAs/SM).
// ---------------------------------------------------------------------------
__global__ void __launch_bounds__(256) contract_kernel()
{
    __shared__ __align__(128) char sm[49152];   // 3 bufs x (A 8KB + B 8KB)
    const int tid = threadIdx.x, lane = tid & 31, wid = tid >> 5;
    const int wm = wid & 3, wn = wid >> 2;
    const int lrow = lane & 15, lseg = lane >> 4;

    uint32_t tBase[3][2];
#pragma unroll
    for (int q = 0; q < 3; q++) {
        tBase[q][0] = smem_u32(sm) + q * 16384;
        tBase[q][1] = tBase[q][0] + 8192;
    }

    auto issue = [&](int ch, int q) {
        const long k0 = (long)blockIdx.x * 1024 + ch * 64;
#pragma unroll
        for (int it = 0; it < 4; it++) {
            int t   = tid + it * 256;   // 0..1023
            int m   = t >> 9;           // 0 = G(A), 1 = W(B)
            int rem = t & 511;
            int row = rem >> 3;         // 0..63
            int kg  = rem & 7;
            const __half* src = (m ? g_Wh : g_Gh) + (size_t)row * KTOT + k0 + kg * 8;
            cpasync16(tBase[q][m] + SW128((uint32_t)(row * 128 + kg * 16)), src);
        }
    };

    float acc[4][4];
#pragma unroll
    for (int j = 0; j < 4; j++)
#pragma unroll
        for (int q = 0; q < 4; q++) acc[j][q] = 0.0f;

    issue(0, 0); CP_COMMIT();
    issue(1, 1); CP_COMMIT();
    for (int ch = 0; ch < 16; ch++) {
        if (ch + 2 < 16) {
            issue(ch + 2, (ch + 2) % 3);
            CP_COMMIT();
            CP_WAIT(2);
        } else if (ch + 1 < 16) {
            CP_WAIT(1);
        } else {
            CP_WAIT(0);
        }
        __syncthreads();
        uint32_t aBase = tBase[ch % 3][0], bBase = tBase[ch % 3][1];
#pragma unroll
        for (int ks = 0; ks < 4; ks++) {
            uint32_t afr[4];
            int arow = wm * 16 + lrow;
            ldsm4(afr, aBase + SW128((uint32_t)(arow * 128 + ks * 32 + lseg * 16)));
#pragma unroll
            for (int nj = 0; nj < 2; nj++) {
                uint32_t bfr[4];
                int brow = wn * 32 + nj * 16 + lrow;
                ldsm4(bfr, bBase + SW128((uint32_t)(brow * 128 + ks * 32 + lseg * 16)));
                mma_fp16(acc[nj * 2],     afr, bfr[0], bfr[2]);
                mma_fp16(acc[nj * 2 + 1], afr, bfr[1], bfr[3]);
            }
        }
        __syncthreads();
    }

    float* outp = g_Zp + (size_t)blockIdx.x * 4096;
#pragma unroll
    for (int nj = 0; nj < 4; nj++) {
        int r = wm * 16 + (lane >> 2);
        int c = wn * 32 + nj * 8 + (lane & 3) * 2;
        *(float2*)&outp[r * 64 + c]       = make_float2(acc[nj][0], acc[nj][1]);
        *(float2*)&outp[(r + 8) * 64 + c] = make_float2(acc[nj][2], acc[nj][3]);
    }
}

// ---------------------------------------------------------------------------
// Fused reduce + softmax, vectorized: 64 CTAs x 1024 threads.
// Thread (jt, i4): jt in [0,64) sums 9 of 576 partials, i4 in [0,16) owns a
// float4 of n. 9 independent float4 loads/thread (L2-resident) -> high MLP.
// Deterministic: fixed per-thread order + fixed smem tree.
// ---------------------------------------------------------------------------
__global__ void __launch_bounds__(1024) reduce_softmax_kernel(
    const float* __restrict__ bias, float* __restrict__ out)
{
    const int b  = blockIdx.x;
    const int tid = threadIdx.x;
    const int i4 = tid & 15;        // 16 float4 groups over n
    const int jt = tid >> 4;        // 64 j-threads
    __shared__ float4 sd4[64][17];  // padded pitch (17*16B) to spread banks
    __shared__ float red[64];

    float4 s = make_float4(0.f, 0.f, 0.f, 0.f);
#pragma unroll
    for (int u = 0; u < 9; u++) {
        float4 v = *(const float4*)&g_Zp[(size_t)(jt + u * 64) * 4096 + b * 64 + i4 * 4];
        s.x += v.x; s.y += v.y; s.z += v.z; s.w += v.w;
    }
    sd4[jt][i4] = s;
    __syncthreads();

    for (int off = 32; off > 0; off >>= 1) {
        if (jt < off) {
            float4 a = sd4[jt][i4], c = sd4[jt + off][i4];
            a.x += c.x; a.y += c.y; a.z += c.z; a.w += c.w;
            sd4[jt][i4] = a;
        }
        __syncthreads();
    }

    // sd4[0][n>>2] holds total z-sums; 64-thread softmax
    float z = 0.0f, e = 0.0f;
    if (tid < 64) {
        float4 t4 = sd4[0][tid >> 2];
        float zv = (tid & 3) == 0 ? t4.x : (tid & 3) == 1 ? t4.y : (tid & 3) == 2 ? t4.z : t4.w;
        z = zv * (1.0f / 196.0f) + bias[tid];
        red[tid] = z;
    }
    __syncthreads();
    for (int off = 32; off > 0; off >>= 1) {
        if (tid < off) red[tid] = fmaxf(red[tid], red[tid + off]);
        __syncthreads();
    }
    float m = red[0];
    __syncthreads();
    if (tid < 64) { e = expf(z - m); red[tid] = e; }
    __syncthreads();
    for (int off = 32; off > 0; off >>= 1) {
        if (tid < off) red[tid] += red[tid + off];
        __syncthreads();
    }
    if (tid < 64) out[b * 64 + tid] = e / red[0];
}

// ---------------------------------------------------------------------------
// Launch
// ---------------------------------------------------------------------------
extern "C" void kernel_launch(void* const* d_in, const int* in_sizes, int n_in,
                              void* d_out, int out_size) {
    const float* X    = (const float*)d_in[0];  // [64, 768, 14, 14]
    const float* Y    = (const float*)d_in[1];  // [64, 768, 14, 14]
    const float* w    = (const float*)d_in[2];  // [2, 64, 768, 32]
    const float* bias = (const float*)d_in[3];  // [64]
    float* out = (float*)d_out;                 // [64, 64]

    // Idempotent, not a stream op — safe under graph capture.
    cudaFuncSetAttribute(gemm_unified, cudaFuncAttributeMaxDynamicSharedMemorySize, 98304);

    // Stage 0: fp32 -> fp16 planes
    prep_kernel<<<11520, 256>>>(X, Y, w);

    // Stages 1+2 fused + wave-interleaved: Gram of (X,Y) and of (w0,w1)
    {
        dim3 grid(6, 6, 128);
        gemm_unified<<<grid, 256, 98304>>>();
    }

    // Stage 3: split-K contraction (round-13 3-buffer form)
    contract_kernel<<<576, 256>>>();

    // Stage 3b+4: fused vectorized reduce + softmax
    reduce_softmax_kernel<<<64, 1024>>>(bias, out);
}

// round 17
// speedup vs baseline: 1.0445x; 1.0115x over previous
#include <cuda_runtime.h>
#include <cuda_bf16.h>
#include <cuda_fp16.h>
#include <cstdint>

#define KTOT (768*768)   // 589824
#define LDK1 208         // X/Y padded K (196 -> 208)

// fp16 input planes
static __device__ __align__(16) __half g_Xh[(size_t)64*768*LDK1];  // 20.4 MB
static __device__ __align__(16) __half g_Yh[(size_t)64*768*LDK1];
static __device__ __align__(16) __half g_w0h[(size_t)64*768*32];   // 3.1 MB, unpadded
static __device__ __align__(16) __half g_w1h[(size_t)64*768*32];
// fp16 planes of G[b,c,c'] and W[n,c,c']  (75.5 MB each)
static __device__ __align__(16) __half g_Gh[(size_t)64*KTOT];
static __device__ __align__(16) __half g_Wh[(size_t)64*KTOT];
static __device__ float g_Zp[576*64*64];   // split-K partials (deterministic)

// ---------------------------------------------------------------------------
// helpers
// ---------------------------------------------------------------------------
__device__ __forceinline__ uint32_t smem_u32(const void* p) {
    uint32_t a;
    asm("{ .reg .u64 t; cvta.to.shared.u64 t, %1; cvt.u32.u64 %0, t; }" : "=r"(a) : "l"(p));
    return a;
}
#define SW128(o) ((o) ^ (((o) >> 3) & 0x70))

__device__ __forceinline__ void cpasync16(uint32_t dst, const void* src) {
    asm volatile("cp.async.cg.shared.global [%0], [%1], 16;" :: "r"(dst), "l"(src));
}
#define CP_COMMIT() asm volatile("cp.async.commit_group;" ::: "memory")
#define CP_WAIT(n)  asm volatile("cp.async.wait_group %0;" :: "n"(n) : "memory")

__device__ __forceinline__ void ldsm4(uint32_t* r, uint32_t addr) {
    asm volatile("ldmatrix.sync.aligned.m8n8.x4.shared.b16 {%0,%1,%2,%3}, [%4];"
                 : "=r"(r[0]), "=r"(r[1]), "=r"(r[2]), "=r"(r[3]) : "r"(addr));
}
__device__ __forceinline__ void mma_fp16(float* c, const uint32_t* a, uint32_t b0, uint32_t b1) {
    asm volatile("mma.sync.aligned.m16n8k16.row.col.f32.f16.f16.f32 "
                 "{%0,%1,%2,%3}, {%4,%5,%6,%7}, {%8,%9}, {%0,%1,%2,%3};"
                 : "+f"(c[0]), "+f"(c[1]), "+f"(c[2]), "+f"(c[3])
                 : "r"(a[0]), "r"(a[1]), "r"(a[2]), "r"(a[3]), "r"(b0), "r"(b1));
}

// 128x128 warp-MMA over [128 rows][64 halves] SW128 tiles; nks k-steps of 16.
// B fragments are software-pipelined (ping-pong): B(nj+1) is loaded BEFORE
// the MMAs consuming B(nj), giving each LDSM ~4 MMA latencies of cover
// (volatile asm pins source order, so the pipelining must be manual).
__device__ __forceinline__ void compute_chunk(
    float acc[2][8][4], uint32_t aBase, uint32_t bBase, int wm, int wn, int lane, int nks)
{
    const int lrow = lane & 15, lseg = lane >> 4;
#pragma unroll
    for (int ks = 0; ks < 4; ks++) {
        if (ks >= nks) break;
        uint32_t afr[2][4];
#pragma unroll
        for (int mi = 0; mi < 2; mi++) {
            int row = wm * 32 + mi * 16 + lrow;
            ldsm4(afr[mi], aBase + SW128((uint32_t)(row * 128 + ks * 32 + lseg * 16)));
        }
        uint32_t bfr[2][4];
        {
            int row = wn * 64 + lrow;           // nj = 0
            ldsm4(bfr[0], bBase + SW128((uint32_t)(row * 128 + ks * 32 + lseg * 16)));
        }
#pragma unroll
        for (int nj = 0; nj < 4; nj++) {
            if (nj < 3) {                       // prefetch B(nj+1)
                int row = wn * 64 + (nj + 1) * 16 + lrow;
                ldsm4(bfr[(nj + 1) & 1],
                      bBase + SW128((uint32_t)(row * 128 + ks * 32 + lseg * 16)));
            }
            const uint32_t* bc = bfr[nj & 1];
#pragma unroll
            for (int mi = 0; mi < 2; mi++) {
                mma_fp16(acc[mi][nj * 2],     afr[mi], bc[0], bc[2]);
                mma_fp16(acc[mi][nj * 2 + 1], afr[mi], bc[1], bc[3]);
            }
        }
    }
}

// ---------------------------------------------------------------------------
// Prep: fp32 -> fp16 planes. X/Y: 196 -> 208 cols; w: 32 cols unpadded.
// grid 11520 x 256 (exact).
// ---------------------------------------------------------------------------
__global__ void prep_kernel(const float* __restrict__ X, const float* __restrict__ Y,
                            const float* __restrict__ w)
{
    const long n1 = (long)64 * 768 * 26;   // uint4 slots per X/Y plane
    const long n3 = (long)64 * 768 * 4;    // uint4 slots per w plane (32 cols)
    long s = (long)blockIdx.x * 256 + threadIdx.x;
    union { __half h[8]; uint4 u; } o;
    if (s < 2 * n1) {
        const float* src = (s < n1) ? X : Y;
        __half* dst = (s < n1) ? g_Xh : g_Yh;
        long t = (s < n1) ? s : s - n1;
        long row = t / 26;
        int slot = (int)(t % 26);
        int k0 = slot * 8;
        if (slot < 23) {
            float4 p0 = *(const float4*)&src[row * 196 + k0];
            float4 p1 = *(const float4*)&src[row * 196 + k0 + 4];
            o.h[0] = __float2half(p0.x); o.h[1] = __float2half(p0.y);
            o.h[2] = __float2half(p0.z); o.h[3] = __float2half(p0.w);
            o.h[4] = __float2half(p1.x); o.h[5] = __float2half(p1.y);
            o.h[6] = __float2half(p1.z); o.h[7] = __float2half(p1.w);
        } else {
#pragma unroll
            for (int j = 0; j < 8; j++) {
                int k = k0 + j;
                o.h[j] = (k < 196) ? __float2half(src[row * 196 + k]) : __half(0.0f);
            }
        }
        *(uint4*)&dst[row * LDK1 + k0] = o.u;
    } else {
        long t = s - 2 * n1;
        const float* src = (t < n3) ? w : (w + (long)64 * 768 * 32);
        __half* dst = (t < n3) ? g_w0h : g_w1h;
        long u2 = (t < n3) ? t : t - n3;
        long row = u2 >> 2;
        int k0 = (int)(u2 & 3) << 3;
        float4 p0 = *(const float4*)&src[row * 32 + k0];
        float4 p1 = *(const float4*)&src[row * 32 + k0 + 4];
        o.h[0] = __float2half(p0.x); o.h[1] = __float2half(p0.y);
        o.h[2] = __float2half(p0.z); o.h[3] = __float2half(p0.w);
        o.h[4] = __float2half(p1.x); o.h[5] = __float2half(p1.y);
        o.h[6] = __float2half(p1.z); o.h[7] = __float2half(p1.w);
        *(uint4*)&dst[row * 32 + k0] = o.u;
    }
}

// ---------------------------------------------------------------------------
// Unified Gram GEMM (round-13 structure): grid (6,6,128), 2 CTAs/SM:
//   bz even: G[bz/2] = Xh @ Yh^T (ldk=208; 4 chunks, ksteps {4,4,4,1})
//   bz odd : W[bz/2] = w0h @ w1h^T (ldk=32; 1 chunk, 2 ksteps)
// 3-stage cp.async, distance-2 prefetch, issue-before-wait. dyn smem 98304.
// ---------------------------------------------------------------------------
__global__ void __launch_bounds__(256, 2) gemm_unified()
{
    extern __shared__ char dsm[];
    const int tid = threadIdx.x, lane = tid & 31, wid = tid >> 5;
    const int wm = wid & 3, wn = wid >> 2;
    const int bx = blockIdx.x, by = blockIdx.y, bzr = blockIdx.z;
    const bool isW = (bzr & 1);
    const int  idx = bzr >> 1;        // batch b (G) or output n (W)

    const __half* Ap;
    const __half* Bp;
    int ldk, nCh;
    if (isW) {
        Ap = g_w0h + (size_t)idx * 768 * 32;
        Bp = g_w1h + (size_t)idx * 768 * 32;
        ldk = 32; nCh = 1;
    } else {
        Ap = g_Xh + (size_t)idx * 768 * LDK1;
        Bp = g_Yh + (size_t)idx * 768 * LDK1;
        ldk = LDK1; nCh = 4;
    }
    const __half* Ab = Ap + (size_t)(by * 128) * ldk;
    const __half* Bb = Bp + (size_t)(bx * 128) * ldk;

    uint32_t tBase[3][2];   // [buf][A/B]
#pragma unroll
    for (int q = 0; q < 3; q++) {
        tBase[q][0] = smem_u32(dsm) + q * 32768;
        tBase[q][1] = tBase[q][0] + 16384;
    }

    auto issue = [&](int ch, int q, int kgmax) {
#pragma unroll
        for (int it = 0; it < 8; it++) {
            int t   = tid + it * 256;     // 0..2047
            int m   = t >> 10;            // 0=A, 1=B
            int rem = t & 1023;
            int row = rem >> 3;
            int kg  = rem & 7;
            if (kg < kgmax) {
                const __half* src = (m ? Bb : Ab) + (size_t)row * ldk + ch * 64 + kg * 8;
                cpasync16(tBase[q][m] + SW128((uint32_t)(row * 128 + kg * 16)), src);
            }
        }
    };

    float acc[2][8][4];
#pragma unroll
    for (int i = 0; i < 2; i++)
#pragma unroll
        for (int j = 0; j < 8; j++)
#pragma unroll
            for (int q = 0; q < 4; q++) acc[i][j][q] = 0.0f;

    // pipeline prologue: prefetch up to 2 chunks
    issue(0, 0, isW ? 4 : 8);
    CP_COMMIT();
    if (nCh > 1) { issue(1, 1, 8); CP_COMMIT(); }

    for (int ch = 0; ch < nCh; ch++) {
        if (ch + 2 < nCh) {
            issue(ch + 2, (ch + 2) % 3, (ch + 2 < 3) ? 8 : 2);
            CP_COMMIT();
            CP_WAIT(2);
        } else if (ch + 1 < nCh) {
            CP_WAIT(1);
        } else {
            CP_WAIT(0);
        }
        __syncthreads();
        int nks = isW ? 2 : (ch < 3 ? 4 : 1);
        compute_chunk(acc, tBase[ch % 3][0], tBase[ch % 3][1], wm, wn, lane, nks);
        __syncthreads();
    }

    // epilogue: fragments -> half2 -> smem fp16 [128][68 u32 pitch] -> global
    uint32_t* Sh = (uint32_t*)dsm;
#pragma unroll
    for (int mi = 0; mi < 2; mi++)
#pragma unroll
        for (int ni = 0; ni < 8; ni++) {
            int r  = wm * 32 + mi * 16 + (lane >> 2);
            int c2 = wn * 32 + ni * 4 + (lane & 3);
            __half2 h0 = __floats2half2_rn(acc[mi][ni][0], acc[mi][ni][1]);
            __half2 h1 = __floats2half2_rn(acc[mi][ni][2], acc[mi][ni][3]);
            Sh[r * 68 + c2]       = *(uint32_t*)&h0;
            Sh[(r + 8) * 68 + c2] = *(uint32_t*)&h1;
        }
    __syncthreads();

    __half* Oh = (isW ? g_Wh : g_Gh) + (size_t)idx * KTOT;
#pragma unroll
    for (int it = 0; it < 8; it++) {
        int i2  = tid + it * 256;      // 2048 uint4 = 128 rows x 16
        int row = i2 >> 4;
        int c4  = (i2 & 15) * 4;
        uint4 v = *(const uint4*)&Sh[row * 68 + c4];
        *(uint4*)&Oh[(size_t)(by * 128 + row) * 768 + bx * 128 + c4 * 2] = v;
    }
}

// ---------------------------------------------------------------------------
// Stage 3 (round-13 form + B-fragment pipelining): 64x64 output per CTA.
// 576 CTAs x 1024-k slices, 16 chunks of 64, 3-stage cp.async (49KB -> 4 CTAs/SM).
// ---------------------------------------------------------------------------
__global__ void __launch_bounds__(256) contract_kernel()
{
    __shared__ __align__(128) char sm[49152];   // 3 bufs x (A 8KB + B 8KB)
    const int tid = threadIdx.x, lane = tid & 31, wid = tid >> 5;
    const int wm = wid & 3, wn = wid >> 2;
    const int lrow = lane & 15, lseg = lane >> 4;

    uint32_t tBase[3][2];
#pragma unroll
    for (int q = 0; q < 3; q++) {
        tBase[q][0] = smem_u32(sm) + q * 16384;
        tBase[q][1] = tBase[q][0] + 8192;
    }

    auto issue = [&](int ch, int q) {
        const long k0 = (long)blockIdx.x * 1024 + ch * 64;
#pragma unroll
        for (int it = 0; it < 4; it++) {
            int t   = tid + it * 256;   // 0..1023
            int m   = t >> 9;           // 0 = G(A), 1 = W(B)
            int rem = t & 511;
            int row = rem >> 3;         // 0..63
            int kg  = rem & 7;
            const __half* src = (m ? g_Wh : g_Gh) + (size_t)row * KTOT + k0 + kg * 8;
            cpasync16(tBase[q][m] + SW128((uint32_t)(row * 128 + kg * 16)), src);
        }
    };

    float acc[4][4];
#pragma unroll
    for (int j = 0; j < 4; j++)
#pragma unroll
        for (int q = 0; q < 4; q++) acc[j][q] = 0.0f;

    issue(0, 0); CP_COMMIT();
    issue(1, 1); CP_COMMIT();
    for (int ch = 0; ch < 16; ch++) {
        if (ch + 2 < 16) {
            issue(ch + 2, (ch + 2) % 3);
            CP_COMMIT();
            CP_WAIT(2);
        } else if (ch + 1 < 16) {
            CP_WAIT(1);
        } else {
            CP_WAIT(0);
        }
        __syncthreads();
        uint32_t aBase = tBase[ch % 3][0], bBase = tBase[ch % 3][1];
#pragma unroll
        for (int ks = 0; ks < 4; ks++) {
            uint32_t afr[4];
            int arow = wm * 16 + lrow;
            ldsm4(afr, aBase + SW128((uint32_t)(arow * 128 + ks * 32 + lseg * 16)));
            uint32_t bfr[2][4];
            {
                int brow = wn * 32 + lrow;      // nj = 0
                ldsm4(bfr[0], bBase + SW128((uint32_t)(brow * 128 + ks * 32 + lseg * 16)));
            }
#pragma unroll
            for (int nj = 0; nj < 2; nj++) {
                if (nj < 1) {                   // prefetch B(nj+1)
                    int brow = wn * 32 + 16 + lrow;
                    ldsm4(bfr[1], bBase + SW128((uint32_t)(brow * 128 + ks * 32 + lseg * 16)));
                }
                const uint32_t* bc = bfr[nj];
                mma_fp16(acc[nj * 2],     afr, bc[0], bc[2]);
                mma_fp16(acc[nj * 2 + 1], afr, bc[1], bc[3]);
            }
        }
        __syncthreads();
    }

    float* outp = g_Zp + (size_t)blockIdx.x * 4096;
#pragma unroll
    for (int nj = 0; nj < 4; nj++) {
        int r = wm * 16 + (lane >> 2);
        int c = wn * 32 + nj * 8 + (lane & 3) * 2;
        *(float2*)&outp[r * 64 + c]       = make_float2(acc[nj][0], acc[nj][1]);
        *(float2*)&outp[(r + 8) * 64 + c] = make_float2(acc[nj][2], acc[nj][3]);
    }
}

// ---------------------------------------------------------------------------
// Fused reduce (576 partials, 16-way split) + softmax. 64 CTAs x 1024 thr.
// ---------------------------------------------------------------------------
__global__ void __launch_bounds__(1024) reduce_softmax_kernel(
    const float* __restrict__ bias, float* __restrict__ out)
{
    const int b = blockIdx.x;
    const int g = threadIdx.x >> 6, n = threadIdx.x & 63;   // 16 groups x 64 n
    __shared__ float sd[16][64];
    __shared__ float red[64];

    float s = 0.0f;
#pragma unroll
    for (int u = 0; u < 36; u++)
        s += g_Zp[(size_t)(g + u * 16) * 4096 + b * 64 + n];
    sd[g][n] = s;
    __syncthreads();

    for (int off = 8; off > 0; off >>= 1) {
        if (g < off) sd[g][n] += sd[g + off][n];
        __syncthreads();
    }

    float z = 0.0f;
    if (g == 0) {
        z = sd[0][n] * (1.0f / 196.0f) + bias[n];
        red[n] = z;
    }
    __syncthreads();
    for (int off = 32; off > 0; off >>= 1) {
        if (g == 0 && n < off) red[n] = fmaxf(red[n], red[n + off]);
        __syncthreads();
    }
    float m = red[0];
    __syncthreads();
    float e = 0.0f;
    if (g == 0) { e = expf(z - m); red[n] = e; }
    __syncthreads();
    for (int off = 32; off > 0; off >>= 1) {
        if (g == 0 && n < off) red[n] += red[n + off];
        __syncthreads();
    }
    if (g == 0) out[b * 64 + n] = e / red[0];
}

// ---------------------------------------------------------------------------
// Launch
// ---------------------------------------------------------------------------
extern "C" void kernel_launch(void* const* d_in, const int* in_sizes, int n_in,
                              void* d_out, int out_size) {
    const float* X    = (const float*)d_in[0];  // [64, 768, 14, 14]
    const float* Y    = (const float*)d_in[1];  // [64, 768, 14, 14]
    const float* w    = (const float*)d_in[2];  // [2, 64, 768, 32]
    const float* bias = (const float*)d_in[3];  // [64]
    float* out = (float*)d_out;                 // [64, 64]

    // Idempotent, not a stream op — safe under graph capture.
    cudaFuncSetAttribute(gemm_unified, cudaFuncAttributeMaxDynamicSharedMemorySize, 98304);

    // Stage 0: fp32 -> fp16 planes
    prep_kernel<<<11520, 256>>>(X, Y, w);

    // Stages 1+2 fused + wave-interleaved: Gram of (X,Y) and of (w0,w1)
    {
        dim3 grid(6, 6, 128);
        gemm_unified<<<grid, 256, 98304>>>();
    }

    // Stage 3: split-K contraction
    contract_kernel<<<576, 256>>>();

    // Stage 3b+4: fused deterministic reduce + softmax
    reduce_softmax_kernel<<<64, 1024>>>(bias, out);
}